// round 16
// baseline (speedup 1.0000x reference)
#include <cuda_runtime.h>
#include <cuda_fp16.h>
#include <cstdint>

#define N_NODES 100000
#define N_EDGES 1250000
#define FEATS   64
#define CAP     64            // bucket capacity per node (Poisson(12.5): P(>63) ~ 1e-30)

// ---------------------------------------------------------------------------
// Device-global scratch (no allocations allowed).
// ---------------------------------------------------------------------------
__device__ int   g_count[N_NODES];              // per-node in-degree
__device__ int   g_bucket[N_NODES * CAP];       // src ids, fixed stride
__device__ uint4 g_hwh[N_NODES * 8];            // h @ W^T in fp16 (64 halves = 8 uint4/node)

// m16n8k16 f16 mma with f32 accumulate (classic Ampere layout, valid sm_103a)
#define MMA_16816(c0, c1, c2, c3, a0, a1, a2, a3, b0, b1) \
    asm volatile( \
        "mma.sync.aligned.m16n8k16.row.col.f32.f16.f16.f32 " \
        "{%0,%1,%2,%3}, {%4,%5,%6,%7}, {%8,%9}, {%0,%1,%2,%3};" \
        : "+f"(c0), "+f"(c1), "+f"(c2), "+f"(c3) \
        : "r"(a0), "r"(a1), "r"(a2), "r"(a3), "r"(b0), "r"(b1))

__device__ __forceinline__ unsigned f2_to_h2(float2 f) {
    __half2 h = __floats2half2_rn(f.x, f.y);
    return *reinterpret_cast<unsigned*>(&h);
}

// ---------------------------------------------------------------------------
// Side stream + events + symbol address, created once at load time.
// ---------------------------------------------------------------------------
static cudaStream_t g_s2 = nullptr;
static cudaEvent_t  g_evFork = nullptr, g_evJoin = nullptr;
static void*        g_countPtr = nullptr;
namespace {
struct StreamInit {
    StreamInit() {
        if (cudaStreamCreateWithFlags(&g_s2, cudaStreamNonBlocking) != cudaSuccess)
            g_s2 = nullptr;
        if (cudaEventCreateWithFlags(&g_evFork, cudaEventDisableTiming) != cudaSuccess)
            g_evFork = nullptr;
        if (cudaEventCreateWithFlags(&g_evJoin, cudaEventDisableTiming) != cudaSuccess)
            g_evJoin = nullptr;
        if (cudaGetSymbolAddress(&g_countPtr, g_count) != cudaSuccess)
            g_countPtr = nullptr;
    }
} s_streamInit;
}

// ---------------------------------------------------------------------------
// K1 (fallback only): zero the degree histogram
// ---------------------------------------------------------------------------
__global__ void zero_count_kernel() {
    unsigned i = blockIdx.x * blockDim.x + threadIdx.x;
    if (i < N_NODES / 4) {
        reinterpret_cast<int4*>(g_count)[i] = make_int4(0, 0, 0, 0);
    }
}

// ---------------------------------------------------------------------------
// K2: direct bucket fill.  8 edges per thread (2 x int4 each of src/dst)
// -> ATOMG MLP 8.
// ---------------------------------------------------------------------------
__global__ __launch_bounds__(256)
void fill_kernel(const int4* __restrict__ src4, const int4* __restrict__ dst4) {
    unsigned q = (blockIdx.x * blockDim.x + threadIdx.x) * 2u;  // int4 pair idx
    if (q >= N_EDGES / 4) return;

    int4 sA = __ldg(&src4[q + 0]);
    int4 dA = __ldg(&dst4[q + 0]);
    int4 sB = __ldg(&src4[q + 1]);
    int4 dB = __ldg(&dst4[q + 1]);

    int pA0 = atomicAdd(&g_count[dA.x], 1);
    int pA1 = atomicAdd(&g_count[dA.y], 1);
    int pA2 = atomicAdd(&g_count[dA.z], 1);
    int pA3 = atomicAdd(&g_count[dA.w], 1);
    int pB0 = atomicAdd(&g_count[dB.x], 1);
    int pB1 = atomicAdd(&g_count[dB.y], 1);
    int pB2 = atomicAdd(&g_count[dB.z], 1);
    int pB3 = atomicAdd(&g_count[dB.w], 1);

    if (pA0 < CAP) g_bucket[dA.x * CAP + pA0] = sA.x;
    if (pA1 < CAP) g_bucket[dA.y * CAP + pA1] = sA.y;
    if (pA2 < CAP) g_bucket[dA.z * CAP + pA2] = sA.z;
    if (pA3 < CAP) g_bucket[dA.w * CAP + pA3] = sA.w;
    if (pB0 < CAP) g_bucket[dB.x * CAP + pB0] = sB.x;
    if (pB1 < CAP) g_bucket[dB.y * CAP + pB1] = sB.y;
    if (pB2 < CAP) g_bucket[dB.z * CAP + pB2] = sB.z;
    if (pB3 < CAP) g_bucket[dB.w * CAP + pB3] = sB.w;
}

// ---------------------------------------------------------------------------
// K3: hw = h @ W^T via tensor cores (m16n8k16, fp16 in / fp32 acc).
// Warp = 16 nodes x 64 outs.  No smem, no LDS: fragments are built in
// registers from f32 gmem loads + cvt (h is L2-resident, W is L1-hot).
// Per warp: 4 K-tiles x 8 N-tiles = 32 HMMA.  Epilogue: fp32->half2 -> g_hwh.
// Fragment map (standard):  g = lane>>2, t = lane&3
//   A: a0=(m=g,k=2t..), a1=(m=g+8,k=2t..), a2=(m=g,k=2t+8..), a3=(m=g+8,k=2t+8..)
//   B: b0=(k=2t..,n=g), b1=(k=2t+8..,n=g)      (B[k][n] = W[n][k], row.col)
//   D: c0=(g,2t), c1=(g,2t+1), c2=(g+8,2t), c3=(g+8,2t+1)
// ---------------------------------------------------------------------------
__global__ __launch_bounds__(256)
void gemm_tc_kernel(const float* __restrict__ h, const float* __restrict__ W) {
    const int warp = threadIdx.x >> 5;
    const int lane = threadIdx.x & 31;
    const int g = lane >> 2;       // 0..7
    const int t = lane & 3;        // 0..3

    unsigned base = (blockIdx.x * 8u + (unsigned)warp) * 16u;
    if (base >= N_NODES) return;

    unsigned r0 = base + (unsigned)g;
    unsigned r1 = r0 + 8u;
    unsigned r0c = (r0 < N_NODES) ? r0 : (N_NODES - 1);
    unsigned r1c = (r1 < N_NODES) ? r1 : (N_NODES - 1);

    float c[8][4];
    #pragma unroll
    for (int nt = 0; nt < 8; nt++)
        #pragma unroll
        for (int j = 0; j < 4; j++) c[nt][j] = 0.f;

    #pragma unroll
    for (int kt = 0; kt < 4; kt++) {
        const int k0 = kt * 16 + 2 * t;
        // A fragments: convert f32 -> packed half2 in registers
        unsigned a0 = f2_to_h2(*reinterpret_cast<const float2*>(&h[r0c * 64u + k0]));
        unsigned a1 = f2_to_h2(*reinterpret_cast<const float2*>(&h[r1c * 64u + k0]));
        unsigned a2 = f2_to_h2(*reinterpret_cast<const float2*>(&h[r0c * 64u + k0 + 8]));
        unsigned a3 = f2_to_h2(*reinterpret_cast<const float2*>(&h[r1c * 64u + k0 + 8]));

        #pragma unroll
        for (int nt = 0; nt < 8; nt++) {
            const int n = nt * 8 + g;
            unsigned b0 = f2_to_h2(*reinterpret_cast<const float2*>(&W[n * 64 + k0]));
            unsigned b1 = f2_to_h2(*reinterpret_cast<const float2*>(&W[n * 64 + k0 + 8]));
            MMA_16816(c[nt][0], c[nt][1], c[nt][2], c[nt][3],
                      a0, a1, a2, a3, b0, b1);
        }
    }

    // epilogue: pack fp32 pairs -> half2, store directly into g_hwh
    __half2* hw2 = reinterpret_cast<__half2*>(g_hwh);
    #pragma unroll
    for (int nt = 0; nt < 8; nt++) {
        unsigned col2 = (unsigned)(nt * 4 + t);     // half2 index within row
        if (r0 < N_NODES)
            hw2[r0 * 32u + col2] = __floats2half2_rn(c[nt][0], c[nt][1]);
        if (r1 < N_NODES)
            hw2[r1 * 32u + col2] = __floats2half2_rn(c[nt][2], c[nt][3]);
    }
}

// ---------------------------------------------------------------------------
// K4: gather-reduce over fp16 hw rows + bias + relu.
// 8 lanes per node; lane owns one uint4 (8 halves).  Indices via int4;
// unroll x8 -> data-load MLP 8.  Pairwise HADD2 then fp32 accumulate.
// ---------------------------------------------------------------------------
__global__ __launch_bounds__(256)
void gather_kernel(const float4* __restrict__ b4, float4* __restrict__ out4) {
    unsigned t = blockIdx.x * blockDim.x + threadIdx.x;   // < N*8 = 800k
    unsigned node = t >> 3;
    unsigned lane = t & 7;
    if (node >= N_NODES) return;

    int deg = __ldg(&g_count[node]);
    if (deg > CAP) deg = CAP;
    const int* row = g_bucket + node * CAP;

    float2 acc[4];
    #pragma unroll
    for (int j = 0; j < 4; j++) acc[j] = make_float2(0.f, 0.f);

    int i = 0;
    for (; i + 8 <= deg; i += 8) {
        int4 ia = __ldg(reinterpret_cast<const int4*>(row + i));
        int4 ib = __ldg(reinterpret_cast<const int4*>(row + i + 4));
        uint4 v0 = __ldg(&g_hwh[(unsigned)ia.x * 8u + lane]);
        uint4 v1 = __ldg(&g_hwh[(unsigned)ia.y * 8u + lane]);
        uint4 v2 = __ldg(&g_hwh[(unsigned)ia.z * 8u + lane]);
        uint4 v3 = __ldg(&g_hwh[(unsigned)ia.w * 8u + lane]);
        uint4 v4 = __ldg(&g_hwh[(unsigned)ib.x * 8u + lane]);
        uint4 v5 = __ldg(&g_hwh[(unsigned)ib.y * 8u + lane]);
        uint4 v6 = __ldg(&g_hwh[(unsigned)ib.z * 8u + lane]);
        uint4 v7 = __ldg(&g_hwh[(unsigned)ib.w * 8u + lane]);
        const __half2* p0 = reinterpret_cast<const __half2*>(&v0);
        const __half2* p1 = reinterpret_cast<const __half2*>(&v1);
        const __half2* p2 = reinterpret_cast<const __half2*>(&v2);
        const __half2* p3 = reinterpret_cast<const __half2*>(&v3);
        const __half2* p4 = reinterpret_cast<const __half2*>(&v4);
        const __half2* p5 = reinterpret_cast<const __half2*>(&v5);
        const __half2* p6 = reinterpret_cast<const __half2*>(&v6);
        const __half2* p7 = reinterpret_cast<const __half2*>(&v7);
        #pragma unroll
        for (int j = 0; j < 4; j++) {
            __half2 s01 = __hadd2(p0[j], p1[j]);   // depth-1 fp16 tree
            __half2 s23 = __hadd2(p2[j], p3[j]);
            __half2 s45 = __hadd2(p4[j], p5[j]);
            __half2 s67 = __hadd2(p6[j], p7[j]);
            float2 f01 = __half22float2(s01);
            float2 f23 = __half22float2(s23);
            float2 f45 = __half22float2(s45);
            float2 f67 = __half22float2(s67);
            acc[j].x += (f01.x + f23.x) + (f45.x + f67.x);
            acc[j].y += (f01.y + f23.y) + (f45.y + f67.y);
        }
    }
    for (; i + 4 <= deg; i += 4) {
        int4 ia = __ldg(reinterpret_cast<const int4*>(row + i));
        uint4 v0 = __ldg(&g_hwh[(unsigned)ia.x * 8u + lane]);
        uint4 v1 = __ldg(&g_hwh[(unsigned)ia.y * 8u + lane]);
        uint4 v2 = __ldg(&g_hwh[(unsigned)ia.z * 8u + lane]);
        uint4 v3 = __ldg(&g_hwh[(unsigned)ia.w * 8u + lane]);
        const __half2* p0 = reinterpret_cast<const __half2*>(&v0);
        const __half2* p1 = reinterpret_cast<const __half2*>(&v1);
        const __half2* p2 = reinterpret_cast<const __half2*>(&v2);
        const __half2* p3 = reinterpret_cast<const __half2*>(&v3);
        #pragma unroll
        for (int j = 0; j < 4; j++) {
            __half2 s01 = __hadd2(p0[j], p1[j]);
            __half2 s23 = __hadd2(p2[j], p3[j]);
            float2 f01 = __half22float2(s01);
            float2 f23 = __half22float2(s23);
            acc[j].x += f01.x + f23.x;
            acc[j].y += f01.y + f23.y;
        }
    }
    for (; i < deg; i++) {
        int s = __ldg(&row[i]);
        uint4 v = __ldg(&g_hwh[(unsigned)s * 8u + lane]);
        const __half2* p = reinterpret_cast<const __half2*>(&v);
        #pragma unroll
        for (int j = 0; j < 4; j++) {
            float2 f = __half22float2(p[j]);
            acc[j].x += f.x;
            acc[j].y += f.y;
        }
    }

    float4 bia = __ldg(&b4[lane * 2 + 0]);
    float4 bib = __ldg(&b4[lane * 2 + 1]);
    float4 r0, r1;
    r0.x = fmaxf(acc[0].x + bia.x, 0.f);
    r0.y = fmaxf(acc[0].y + bia.y, 0.f);
    r0.z = fmaxf(acc[1].x + bia.z, 0.f);
    r0.w = fmaxf(acc[1].y + bia.w, 0.f);
    r1.x = fmaxf(acc[2].x + bib.x, 0.f);
    r1.y = fmaxf(acc[2].y + bib.y, 0.f);
    r1.z = fmaxf(acc[3].x + bib.z, 0.f);
    r1.w = fmaxf(acc[3].y + bib.w, 0.f);
    out4[node * 16u + lane * 2 + 0] = r0;
    out4[node * 16u + lane * 2 + 1] = r1;
}

// ---------------------------------------------------------------------------
// Launch:  stream0: memset(count) -> fill ---\
//          s2:      gemm (tensor-core) -------+--> gather(+bias+relu)
// ---------------------------------------------------------------------------
extern "C" void kernel_launch(void* const* d_in, const int* in_sizes, int n_in,
                              void* d_out, int out_size) {
    const float* h   = (const float*)d_in[0];
    const int*   src = (const int*)d_in[1];
    const int*   dst = (const int*)d_in[2];
    const float* W   = (const float*)d_in[3];
    const float* b   = (const float*)d_in[4];
    float4*      out = (float4*)d_out;

    (void)in_sizes; (void)n_in; (void)out_size;

    const bool fork = (g_s2 && g_evFork && g_evJoin);
    const unsigned fill_threads = N_EDGES / 8;            // 8 edges per thread
    const unsigned gemm_blocks = (N_NODES + 127) / 128;   // 128 nodes per block

    if (fork) {
        cudaEventRecord(g_evFork, 0);
        cudaStreamWaitEvent(g_s2, g_evFork, 0);
        gemm_tc_kernel<<<gemm_blocks, 256, 0, g_s2>>>(h, W);
        cudaEventRecord(g_evJoin, g_s2);

        if (g_countPtr)
            cudaMemsetAsync(g_countPtr, 0, N_NODES * sizeof(int), 0);
        else
            zero_count_kernel<<<(N_NODES / 4 + 255) / 256, 256>>>();
        fill_kernel<<<(fill_threads + 255) / 256, 256>>>(
            (const int4*)src, (const int4*)dst);

        cudaStreamWaitEvent(0, g_evJoin, 0);
    } else {
        if (g_countPtr)
            cudaMemsetAsync(g_countPtr, 0, N_NODES * sizeof(int), 0);
        else
            zero_count_kernel<<<(N_NODES / 4 + 255) / 256, 256>>>();
        fill_kernel<<<(fill_threads + 255) / 256, 256>>>(
            (const int4*)src, (const int4*)dst);
        gemm_tc_kernel<<<gemm_blocks, 256>>>(h, W);
    }

    gather_kernel<<<(N_NODES * 8 + 255) / 256, 256>>>(
        (const float4*)b, out);
}

// round 17
// speedup vs baseline: 1.0181x; 1.0181x over previous
#include <cuda_runtime.h>
#include <cuda_fp16.h>
#include <cstdint>

#define N_NODES 100000
#define N_EDGES 1250000
#define FEATS   64
#define CAP     64            // bucket capacity per node (Poisson(12.5): P(>63) ~ 1e-30)

// ---------------------------------------------------------------------------
// Device-global scratch (no allocations allowed).
// ---------------------------------------------------------------------------
__device__ int   g_count[N_NODES];              // per-node in-degree
__device__ int   g_bucket[N_NODES * CAP];       // src ids, fixed stride
__device__ uint4 g_hwh[N_NODES * 8];            // h @ W^T in fp16 (64 halves = 8 uint4/node)

// m16n8k16 f16 mma with f32 accumulate (classic Ampere layout, valid sm_103a)
#define MMA_16816(c0, c1, c2, c3, a0, a1, a2, a3, b0, b1) \
    asm volatile( \
        "mma.sync.aligned.m16n8k16.row.col.f32.f16.f16.f32 " \
        "{%0,%1,%2,%3}, {%4,%5,%6,%7}, {%8,%9}, {%0,%1,%2,%3};" \
        : "+f"(c0), "+f"(c1), "+f"(c2), "+f"(c3) \
        : "r"(a0), "r"(a1), "r"(a2), "r"(a3), "r"(b0), "r"(b1))

__device__ __forceinline__ unsigned f2_to_h2(float2 f) {
    __half2 h = __floats2half2_rn(f.x, f.y);
    return *reinterpret_cast<unsigned*>(&h);
}

// ---------------------------------------------------------------------------
// Side stream + events + symbol address, created once at load time.
// ---------------------------------------------------------------------------
static cudaStream_t g_s2 = nullptr;
static cudaEvent_t  g_evFork = nullptr, g_evJoin = nullptr;
static void*        g_countPtr = nullptr;
namespace {
struct StreamInit {
    StreamInit() {
        if (cudaStreamCreateWithFlags(&g_s2, cudaStreamNonBlocking) != cudaSuccess)
            g_s2 = nullptr;
        if (cudaEventCreateWithFlags(&g_evFork, cudaEventDisableTiming) != cudaSuccess)
            g_evFork = nullptr;
        if (cudaEventCreateWithFlags(&g_evJoin, cudaEventDisableTiming) != cudaSuccess)
            g_evJoin = nullptr;
        if (cudaGetSymbolAddress(&g_countPtr, g_count) != cudaSuccess)
            g_countPtr = nullptr;
    }
} s_streamInit;
}

// ---------------------------------------------------------------------------
// K1 (fallback only): zero the degree histogram
// ---------------------------------------------------------------------------
__global__ void zero_count_kernel() {
    unsigned i = blockIdx.x * blockDim.x + threadIdx.x;
    if (i < N_NODES / 4) {
        reinterpret_cast<int4*>(g_count)[i] = make_int4(0, 0, 0, 0);
    }
}

// ---------------------------------------------------------------------------
// K2: direct bucket fill.  8 edges per thread (2 x int4 each of src/dst)
// -> ATOMG MLP 8.
// ---------------------------------------------------------------------------
__global__ __launch_bounds__(256)
void fill_kernel(const int4* __restrict__ src4, const int4* __restrict__ dst4) {
    unsigned q = (blockIdx.x * blockDim.x + threadIdx.x) * 2u;  // int4 pair idx
    if (q >= N_EDGES / 4) return;

    int4 sA = __ldg(&src4[q + 0]);
    int4 dA = __ldg(&dst4[q + 0]);
    int4 sB = __ldg(&src4[q + 1]);
    int4 dB = __ldg(&dst4[q + 1]);

    int pA0 = atomicAdd(&g_count[dA.x], 1);
    int pA1 = atomicAdd(&g_count[dA.y], 1);
    int pA2 = atomicAdd(&g_count[dA.z], 1);
    int pA3 = atomicAdd(&g_count[dA.w], 1);
    int pB0 = atomicAdd(&g_count[dB.x], 1);
    int pB1 = atomicAdd(&g_count[dB.y], 1);
    int pB2 = atomicAdd(&g_count[dB.z], 1);
    int pB3 = atomicAdd(&g_count[dB.w], 1);

    if (pA0 < CAP) g_bucket[dA.x * CAP + pA0] = sA.x;
    if (pA1 < CAP) g_bucket[dA.y * CAP + pA1] = sA.y;
    if (pA2 < CAP) g_bucket[dA.z * CAP + pA2] = sA.z;
    if (pA3 < CAP) g_bucket[dA.w * CAP + pA3] = sA.w;
    if (pB0 < CAP) g_bucket[dB.x * CAP + pB0] = sB.x;
    if (pB1 < CAP) g_bucket[dB.y * CAP + pB1] = sB.y;
    if (pB2 < CAP) g_bucket[dB.z * CAP + pB2] = sB.z;
    if (pB3 < CAP) g_bucket[dB.w * CAP + pB3] = sB.w;
}

// ---------------------------------------------------------------------------
// K3: hw = h @ W^T via tensor cores (m16n8k16, fp16 in / fp32 acc).
// Warp = 16 nodes x 64 outs.  No smem, no LDS: fragments are built in
// registers from f32 gmem loads + cvt (h is L2-resident, W is L1-hot).
// Per warp: 4 K-tiles x 8 N-tiles = 32 HMMA.  Epilogue: fp32->half2 -> g_hwh.
// Fragment map (standard):  g = lane>>2, t = lane&3
//   A: a0=(m=g,k=2t..), a1=(m=g+8,k=2t..), a2=(m=g,k=2t+8..), a3=(m=g+8,k=2t+8..)
//   B: b0=(k=2t..,n=g), b1=(k=2t+8..,n=g)      (B[k][n] = W[n][k], row.col)
//   D: c0=(g,2t), c1=(g,2t+1), c2=(g+8,2t), c3=(g+8,2t+1)
// ---------------------------------------------------------------------------
__global__ __launch_bounds__(256)
void gemm_tc_kernel(const float* __restrict__ h, const float* __restrict__ W) {
    const int warp = threadIdx.x >> 5;
    const int lane = threadIdx.x & 31;
    const int g = lane >> 2;       // 0..7
    const int t = lane & 3;        // 0..3

    unsigned base = (blockIdx.x * 8u + (unsigned)warp) * 16u;
    if (base >= N_NODES) return;

    unsigned r0 = base + (unsigned)g;
    unsigned r1 = r0 + 8u;
    unsigned r0c = (r0 < N_NODES) ? r0 : (N_NODES - 1);
    unsigned r1c = (r1 < N_NODES) ? r1 : (N_NODES - 1);

    float c[8][4];
    #pragma unroll
    for (int nt = 0; nt < 8; nt++)
        #pragma unroll
        for (int j = 0; j < 4; j++) c[nt][j] = 0.f;

    #pragma unroll
    for (int kt = 0; kt < 4; kt++) {
        const int k0 = kt * 16 + 2 * t;
        // A fragments: convert f32 -> packed half2 in registers
        unsigned a0 = f2_to_h2(*reinterpret_cast<const float2*>(&h[r0c * 64u + k0]));
        unsigned a1 = f2_to_h2(*reinterpret_cast<const float2*>(&h[r1c * 64u + k0]));
        unsigned a2 = f2_to_h2(*reinterpret_cast<const float2*>(&h[r0c * 64u + k0 + 8]));
        unsigned a3 = f2_to_h2(*reinterpret_cast<const float2*>(&h[r1c * 64u + k0 + 8]));

        #pragma unroll
        for (int nt = 0; nt < 8; nt++) {
            const int n = nt * 8 + g;
            unsigned b0 = f2_to_h2(*reinterpret_cast<const float2*>(&W[n * 64 + k0]));
            unsigned b1 = f2_to_h2(*reinterpret_cast<const float2*>(&W[n * 64 + k0 + 8]));
            MMA_16816(c[nt][0], c[nt][1], c[nt][2], c[nt][3],
                      a0, a1, a2, a3, b0, b1);
        }
    }

    // epilogue: pack fp32 pairs -> half2, store directly into g_hwh
    __half2* hw2 = reinterpret_cast<__half2*>(g_hwh);
    #pragma unroll
    for (int nt = 0; nt < 8; nt++) {
        unsigned col2 = (unsigned)(nt * 4 + t);     // half2 index within row
        if (r0 < N_NODES)
            hw2[r0 * 32u + col2] = __floats2half2_rn(c[nt][0], c[nt][1]);
        if (r1 < N_NODES)
            hw2[r1 * 32u + col2] = __floats2half2_rn(c[nt][2], c[nt][3]);
    }
}

// ---------------------------------------------------------------------------
// K4: gather-reduce over fp16 hw rows + bias + relu.
// 8 lanes per node; lane owns one uint4 (8 halves).  Indices via int4;
// unroll x8 -> data-load MLP 8.  Pairwise HADD2 then fp32 accumulate.
// ---------------------------------------------------------------------------
__global__ __launch_bounds__(256)
void gather_kernel(const float4* __restrict__ b4, float4* __restrict__ out4) {
    unsigned t = blockIdx.x * blockDim.x + threadIdx.x;   // < N*8 = 800k
    unsigned node = t >> 3;
    unsigned lane = t & 7;
    if (node >= N_NODES) return;

    int deg = __ldg(&g_count[node]);
    if (deg > CAP) deg = CAP;
    const int* row = g_bucket + node * CAP;

    float2 acc[4];
    #pragma unroll
    for (int j = 0; j < 4; j++) acc[j] = make_float2(0.f, 0.f);

    int i = 0;
    for (; i + 8 <= deg; i += 8) {
        int4 ia = __ldg(reinterpret_cast<const int4*>(row + i));
        int4 ib = __ldg(reinterpret_cast<const int4*>(row + i + 4));
        uint4 v0 = __ldg(&g_hwh[(unsigned)ia.x * 8u + lane]);
        uint4 v1 = __ldg(&g_hwh[(unsigned)ia.y * 8u + lane]);
        uint4 v2 = __ldg(&g_hwh[(unsigned)ia.z * 8u + lane]);
        uint4 v3 = __ldg(&g_hwh[(unsigned)ia.w * 8u + lane]);
        uint4 v4 = __ldg(&g_hwh[(unsigned)ib.x * 8u + lane]);
        uint4 v5 = __ldg(&g_hwh[(unsigned)ib.y * 8u + lane]);
        uint4 v6 = __ldg(&g_hwh[(unsigned)ib.z * 8u + lane]);
        uint4 v7 = __ldg(&g_hwh[(unsigned)ib.w * 8u + lane]);
        const __half2* p0 = reinterpret_cast<const __half2*>(&v0);
        const __half2* p1 = reinterpret_cast<const __half2*>(&v1);
        const __half2* p2 = reinterpret_cast<const __half2*>(&v2);
        const __half2* p3 = reinterpret_cast<const __half2*>(&v3);
        const __half2* p4 = reinterpret_cast<const __half2*>(&v4);
        const __half2* p5 = reinterpret_cast<const __half2*>(&v5);
        const __half2* p6 = reinterpret_cast<const __half2*>(&v6);
        const __half2* p7 = reinterpret_cast<const __half2*>(&v7);
        #pragma unroll
        for (int j = 0; j < 4; j++) {
            __half2 s01 = __hadd2(p0[j], p1[j]);   // depth-1 fp16 tree
            __half2 s23 = __hadd2(p2[j], p3[j]);
            __half2 s45 = __hadd2(p4[j], p5[j]);
            __half2 s67 = __hadd2(p6[j], p7[j]);
            float2 f01 = __half22float2(s01);
            float2 f23 = __half22float2(s23);
            float2 f45 = __half22float2(s45);
            float2 f67 = __half22float2(s67);
            acc[j].x += (f01.x + f23.x) + (f45.x + f67.x);
            acc[j].y += (f01.y + f23.y) + (f45.y + f67.y);
        }
    }
    for (; i + 4 <= deg; i += 4) {
        int4 ia = __ldg(reinterpret_cast<const int4*>(row + i));
        uint4 v0 = __ldg(&g_hwh[(unsigned)ia.x * 8u + lane]);
        uint4 v1 = __ldg(&g_hwh[(unsigned)ia.y * 8u + lane]);
        uint4 v2 = __ldg(&g_hwh[(unsigned)ia.z * 8u + lane]);
        uint4 v3 = __ldg(&g_hwh[(unsigned)ia.w * 8u + lane]);
        const __half2* p0 = reinterpret_cast<const __half2*>(&v0);
        const __half2* p1 = reinterpret_cast<const __half2*>(&v1);
        const __half2* p2 = reinterpret_cast<const __half2*>(&v2);
        const __half2* p3 = reinterpret_cast<const __half2*>(&v3);
        #pragma unroll
        for (int j = 0; j < 4; j++) {
            __half2 s01 = __hadd2(p0[j], p1[j]);
            __half2 s23 = __hadd2(p2[j], p3[j]);
            float2 f01 = __half22float2(s01);
            float2 f23 = __half22float2(s23);
            acc[j].x += f01.x + f23.x;
            acc[j].y += f01.y + f23.y;
        }
    }
    for (; i < deg; i++) {
        int s = __ldg(&row[i]);
        uint4 v = __ldg(&g_hwh[(unsigned)s * 8u + lane]);
        const __half2* p = reinterpret_cast<const __half2*>(&v);
        #pragma unroll
        for (int j = 0; j < 4; j++) {
            float2 f = __half22float2(p[j]);
            acc[j].x += f.x;
            acc[j].y += f.y;
        }
    }

    float4 bia = __ldg(&b4[lane * 2 + 0]);
    float4 bib = __ldg(&b4[lane * 2 + 1]);
    float4 r0, r1;
    r0.x = fmaxf(acc[0].x + bia.x, 0.f);
    r0.y = fmaxf(acc[0].y + bia.y, 0.f);
    r0.z = fmaxf(acc[1].x + bia.z, 0.f);
    r0.w = fmaxf(acc[1].y + bia.w, 0.f);
    r1.x = fmaxf(acc[2].x + bib.x, 0.f);
    r1.y = fmaxf(acc[2].y + bib.y, 0.f);
    r1.z = fmaxf(acc[3].x + bib.z, 0.f);
    r1.w = fmaxf(acc[3].y + bib.w, 0.f);
    out4[node * 16u + lane * 2 + 0] = r0;
    out4[node * 16u + lane * 2 + 1] = r1;
}

// ---------------------------------------------------------------------------
// Launch:  stream0: memset(count) -> fill ---\
//          s2:      gemm (tensor-core) -------+--> gather(+bias+relu)
// ---------------------------------------------------------------------------
extern "C" void kernel_launch(void* const* d_in, const int* in_sizes, int n_in,
                              void* d_out, int out_size) {
    const float* h   = (const float*)d_in[0];
    const int*   src = (const int*)d_in[1];
    const int*   dst = (const int*)d_in[2];
    const float* W   = (const float*)d_in[3];
    const float* b   = (const float*)d_in[4];
    float4*      out = (float4*)d_out;

    (void)in_sizes; (void)n_in; (void)out_size;

    const bool fork = (g_s2 && g_evFork && g_evJoin);
    const unsigned fill_threads = N_EDGES / 8;            // 8 edges per thread
    const unsigned gemm_blocks = (N_NODES + 127) / 128;   // 128 nodes per block

    if (fork) {
        cudaEventRecord(g_evFork, 0);
        cudaStreamWaitEvent(g_s2, g_evFork, 0);
        gemm_tc_kernel<<<gemm_blocks, 256, 0, g_s2>>>(h, W);
        cudaEventRecord(g_evJoin, g_s2);

        if (g_countPtr)
            cudaMemsetAsync(g_countPtr, 0, N_NODES * sizeof(int), 0);
        else
            zero_count_kernel<<<(N_NODES / 4 + 255) / 256, 256>>>();
        fill_kernel<<<(fill_threads + 255) / 256, 256>>>(
            (const int4*)src, (const int4*)dst);

        cudaStreamWaitEvent(0, g_evJoin, 0);
    } else {
        if (g_countPtr)
            cudaMemsetAsync(g_countPtr, 0, N_NODES * sizeof(int), 0);
        else
            zero_count_kernel<<<(N_NODES / 4 + 255) / 256, 256>>>();
        fill_kernel<<<(fill_threads + 255) / 256, 256>>>(
            (const int4*)src, (const int4*)dst);
        gemm_tc_kernel<<<gemm_blocks, 256>>>(h, W);
    }

    gather_kernel<<<(N_NODES * 8 + 255) / 256, 256>>>(
        (const float4*)b, out);
}